// round 1
// baseline (speedup 1.0000x reference)
#include <cuda_runtime.h>
#include <cuda_bf16.h>
#include <cstdint>

// Problem constants
#define IN_H   1536
#define IN_W   1536
#define CH     16
#define OUT_H  768
#define OUT_W  768
#define HW     (IN_H * IN_W)       // 2359296
#define OHW    (OUT_H * OUT_W)     // 589824

// Tile config
#define TX 64          // output pixels in x per block
#define TY 8           // output pixels in y per block
#define IC_CHUNK 4
#define N_CHUNK (CH / IC_CHUNK)
#define IN_COLS (2*TX + 1)         // 129 input cols per tile
#define IN_ROWS (2*TY + 1)         // 17 input rows per tile
#define IN_PITCH (IN_COLS + 1)     // 130 float2, pad to perturb banks

#define S_IN_ELEMS (IC_CHUNK * IN_ROWS * IN_PITCH)   // 8840 float2
#define S_W_ELEMS  (CH * 9 * CH)                     // 2304 float2
#define SMEM_BYTES (size_t)((S_IN_ELEMS + S_W_ELEMS) * sizeof(float2) + 16 * sizeof(float))

// ---------- packed f32x2 helpers ----------
__device__ __forceinline__ unsigned long long fma2(unsigned long long a,
                                                   unsigned long long b,
                                                   unsigned long long c) {
    unsigned long long d;
    asm("fma.rn.f32x2 %0, %1, %2, %3;" : "=l"(d) : "l"(a), "l"(b), "l"(c));
    return d;
}
__device__ __forceinline__ void unpack2(unsigned long long v, float& lo, float& hi) {
    asm("mov.b64 {%0, %1}, %2;" : "=f"(lo), "=f"(hi) : "l"(v));
}
__device__ __forceinline__ unsigned long long lds2(const float2* p) {
    return *reinterpret_cast<const unsigned long long*>(p);
}

__global__ __launch_bounds__(256, 2)
void ibp_conv_kernel(const float* __restrict__ gl, const float* __restrict__ gu,
                     const float* __restrict__ gw, const float* __restrict__ gb,
                     float* __restrict__ out) {
    extern __shared__ float2 sm[];
    float2* s_in = sm;                       // [IC_CHUNK][IN_ROWS][IN_PITCH]
    float2* s_w  = sm + S_IN_ELEMS;          // [(ic*9+t)*16 + oc] = (w, |w|)
    float*  s_b  = (float*)(s_w + S_W_ELEMS);

    const int tid = threadIdx.x;

    // ---- stage weight pairs + bias (once) ----
    for (int i = tid; i < S_W_ELEMS; i += 256) {
        int oc  = i / 144;            // weight is OIHW: i = oc*144 + ic*9 + t
        int rem = i - oc * 144;       // ic*9 + t
        float wv = gw[i];
        s_w[rem * 16 + oc] = make_float2(wv, fabsf(wv));
    }
    if (tid < 16) s_b[tid] = gb[tid];

    const int x0  = blockIdx.x * TX;
    const int y0  = blockIdx.y * TY;
    const int ix0 = 2 * x0 - 1;
    const int iy0 = 2 * y0 - 1;

    const int xg      = tid & 15;            // x-group: pixels xg + 16*p
    const int ty      = (tid >> 4) & 7;      // output row within tile
    const int oc_base = (tid >> 7) * 8;      // oc half

    unsigned long long acc[4][8];
    #pragma unroll
    for (int p = 0; p < 4; p++)
        #pragma unroll
        for (int o = 0; o < 8; o++) acc[p][o] = 0ull;

    #pragma unroll 1
    for (int ck = 0; ck < N_CHUNK; ck++) {
        const int cb = ck * IC_CHUNK;
        __syncthreads();   // protect previous chunk (and weight stage on ck=0)
        // ---- fill input tile: (c, r) pairs with zero padding at borders ----
        #pragma unroll 1
        for (int ic = 0; ic < IC_CHUNK; ic++) {
            const float* lp = gl + (cb + ic) * HW;
            const float* up = gu + (cb + ic) * HW;
            float2* sp = s_in + ic * (IN_ROWS * IN_PITCH);
            for (int j = tid; j < IN_ROWS * IN_COLS; j += 256) {
                int row = j / IN_COLS;
                int col = j - row * IN_COLS;
                int iy = iy0 + row;
                int ix = ix0 + col;
                float2 v = make_float2(0.f, 0.f);
                if ((unsigned)iy < IN_H && (unsigned)ix < IN_W) {
                    int off = iy * IN_W + ix;
                    float lv = __ldg(lp + off);
                    float uv = __ldg(up + off);
                    v = make_float2(0.5f * (lv + uv), 0.5f * (uv - lv));
                }
                sp[row * IN_PITCH + col] = v;
            }
        }
        __syncthreads();
        // ---- compute ----
        #pragma unroll 1
        for (int ic = 0; ic < IC_CHUNK; ic++) {
            #pragma unroll
            for (int dy = 0; dy < 3; dy++) {
                const float2* rowp = s_in + (ic * IN_ROWS + 2 * ty + dy) * IN_PITCH;
                const float2* wp   = s_w + ((cb + ic) * 9 + dy * 3) * 16 + oc_base;
                #pragma unroll
                for (int dx = 0; dx < 3; dx++) {
                    unsigned long long vv[4];
                    #pragma unroll
                    for (int p = 0; p < 4; p++)
                        vv[p] = lds2(rowp + 2 * (xg + 16 * p) + dx);
                    #pragma unroll
                    for (int o = 0; o < 8; o++) {
                        unsigned long long wv = lds2(wp + dx * 16 + o);
                        #pragma unroll
                        for (int p = 0; p < 4; p++)
                            acc[p][o] = fma2(vv[p], wv, acc[p][o]);
                    }
                }
            }
        }
    }

    // ---- epilogue: bound_l = acc_c - acc_r + b ; bound_u = acc_c + acc_r + b ----
    const int oy = y0 + ty;
    #pragma unroll
    for (int o = 0; o < 8; o++) {
        const int oc = oc_base + o;
        const float b = s_b[oc];
        float* outl = out + oc * OHW + oy * OUT_W;
        float* outu = outl + CH * OHW;
        #pragma unroll
        for (int p = 0; p < 4; p++) {
            float ac, ar;
            unpack2(acc[p][o], ac, ar);
            const int ox = x0 + xg + 16 * p;
            outl[ox] = ac - ar + b;
            outu[ox] = ac + ar + b;
        }
    }
}

extern "C" void kernel_launch(void* const* d_in, const int* in_sizes, int n_in,
                              void* d_out, int out_size) {
    const float* l  = (const float*)d_in[0];
    const float* u  = (const float*)d_in[1];
    const float* w  = (const float*)d_in[2];
    const float* b  = (const float*)d_in[3];
    float* out = (float*)d_out;

    cudaFuncSetAttribute(ibp_conv_kernel,
                         cudaFuncAttributeMaxDynamicSharedMemorySize,
                         (int)SMEM_BYTES);
    dim3 grid(OUT_W / TX, OUT_H / TY);   // (12, 96)
    ibp_conv_kernel<<<grid, 256, SMEM_BYTES>>>(l, u, w, b, out);
}